// round 1
// baseline (speedup 1.0000x reference)
#include <cuda_runtime.h>

// Reference math: dx = 0  =>  s^2 = -dt^2 <= 0 everywhere  =>  spacelike_mask == 0
// => penalty == 0 => total_loss = base_loss + LAMBDA_REG * 0 = base_loss.
// The [L,B,H,S,S] attn_weights tensor (d_in[0], ~302M floats) is dead input.
// Exact answer: copy the scalar base_loss (d_in[1]) to d_out[0].
// (fp32 add of +0.0f is the identity, so this is bit-exact vs the reference.)

__global__ void spacetime_loss_kernel(const float* __restrict__ base_loss,
                                      float* __restrict__ out) {
    out[0] = base_loss[0];
}

extern "C" void kernel_launch(void* const* d_in, const int* in_sizes, int n_in,
                              void* d_out, int out_size) {
    // metadata order: d_in[0] = attn_weights [L,B,H,S,S] f32 (unused, mask is all-zero)
    //                 d_in[1] = base_loss scalar f32
    const float* base_loss = (const float*)d_in[1];
    float* out = (float*)d_out;
    spacetime_loss_kernel<<<1, 1>>>(base_loss, out);
}

// round 2
// speedup vs baseline: 1.0556x; 1.0556x over previous
#include <cuda_runtime.h>

// Reference math: dx = 0  =>  s^2 = -dt^2 <= 0 everywhere  =>  spacelike_mask == 0
// => penalty == 0 => total_loss = base_loss + 0.01 * 0 = base_loss (bit-exact in fp32).
// attn_weights (d_in[0], ~302M floats) is dead input.
//
// R2: replace the 1-thread copy kernel with a 4-byte D2D cudaMemcpyAsync so the
// captured graph contains a memcpy node instead of a kernel node — avoids the
// SM kernel launch/teardown path entirely. Graph-capturable: async D2D memcpy
// on the capture (legacy) stream, no allocs, no syncs.

extern "C" void kernel_launch(void* const* d_in, const int* in_sizes, int n_in,
                              void* d_out, int out_size) {
    // d_in[1] = base_loss scalar f32; d_out[0] = total_loss f32
    cudaMemcpyAsync(d_out, d_in[1], sizeof(float),
                    cudaMemcpyDeviceToDevice, (cudaStream_t)0);
}